// round 10
// baseline (speedup 1.0000x reference)
#include <cuda_runtime.h>
#include <cuda_bf16.h>
#include <cstdint>

// 21x21 circular box filter on (8,1,2048,2048) fp32, separable, fused.
// Phase 0: cooperative vectorized stream of 52x160 input tile to SMEM (all
//          256 threads, LDG.128, ~8 independent loads each -> max MLP).
// Phase A2: vertical running box-sums SMEM->SMEM in place (thread per column,
//          21-deep register ring; each smem row read once per column).
// Phase B: horizontal box-sums via warp prefix scan over aligned quads,
//          out[m] = P[m+23]-P[m+2], direct float4 stores.

#define H  2048
#define W  2048
#define NB 8
#define R  10
#define KW (2*R + 1)        // 21
#define TX 128
#define TY 32
#define NROWS (TY + 2*R)    // 52 input rows per tile
#define NQ 40               // quads per row: cols tileX-12 .. tileX+147
#define SSTR 160            // smem row stride in floats (40 quads)
#define THREADS 256

__global__ __launch_bounds__(THREADS, 6)
void box_filter_kernel(const float* __restrict__ in, float* __restrict__ out)
{
    __shared__ float tile[NROWS * SSTR];   // 52*160*4 = 33,280 B

    const int t    = threadIdx.x;
    const int lane = t & 31;
    const int wp   = t >> 5;

    const int bx = blockIdx.x;
    const int by = blockIdx.y;
    const int bz = blockIdx.z;

    const float* img  = in  + (size_t)bz * (size_t)(H * W);
    float*       outg = out + (size_t)bz * (size_t)(H * W);

    const int tileX = bx * TX;
    const int tileY = by * TY;

    // ---------------- Phase 0: stream tile to SMEM (LDG.128, all threads) -----
    // smem col j  <->  global col (tileX - 12 + j) & 2047.  Quads never straddle
    // the x-wrap (offsets and W are multiples of 4).
    {
        const float4* img4  = reinterpret_cast<const float4*>(img);
        float4*       tile4 = reinterpret_cast<float4*>(tile);
        #pragma unroll 4
        for (int k = t; k < NROWS * NQ; k += THREADS) {
            const int row = k / NQ;
            const int q   = k - row * NQ;
            const int gy  = (tileY - R + row) & (H - 1);
            const int gx  = (tileX - 12 + 4 * q) & (W - 1);
            tile4[k] = img4[(gy * W + gx) >> 2];
        }
    }
    __syncthreads();

    // ---------------- Phase A2: vertical running sums (SMEM, in place) --------
    // Thread c owns smem column c+2 (halo col c). Register ring: each smem row
    // read exactly once; vert row i overwrites input row i (already consumed).
    if (t < TX + 2 * R) {
        float* col = tile + t + 2;

        float buf[KW];
        float s = 0.0f;
        #pragma unroll
        for (int j = 0; j < KW; j++) { buf[j] = col[j * SSTR]; s += buf[j]; }
        col[0] = s;

        #pragma unroll
        for (int i = 1; i < TY; i++) {
            const int slot = (i - 1) % KW;          // compile-time after unroll
            const float nv = col[(i + 2 * R) * SSTR];
            s += nv - buf[slot];
            buf[slot] = nv;
            col[i * SSTR] = s;
        }
    }
    __syncthreads();

    // ---------------- Phase B: horizontal sums via warp scan, direct store ----
    // Row r: smem cols 2..149 hold vert sums for halo cols 0..147; cols 0,1 and
    // 150..159 hold untouched finite input that cancels exactly in P-differences.
    // out[m] = P[m+23] - P[m+2] over smem-col basis (38 quads: main 32 + extra 6).
    const unsigned FULL = 0xffffffffu;

    #pragma unroll
    for (int rr = 0; rr < TY / 8; rr++) {
        const int r = wp * (TY / 8) + rr;
        const float* row = tile + r * SSTR;

        float4 q = *reinterpret_cast<const float4*>(row + 4 * lane);
        float4 eq = make_float4(0.f, 0.f, 0.f, 0.f);
        if (lane < 6) eq = *reinterpret_cast<const float4*>(row + 128 + 4 * lane);

        const float s1 = q.x;
        const float s2 = s1 + q.y;
        const float s3 = s2 + q.z;
        const float s4 = s3 + q.w;

        const float t1 = eq.x;
        const float t2 = t1 + eq.y;
        const float t3 = t2 + eq.z;
        const float t4 = t3 + eq.w;

        // inclusive scan of main quad totals -> v; B = P[4l]
        float v = s4;
        #pragma unroll
        for (int d = 1; d < 32; d <<= 1) {
            float u = __shfl_up_sync(FULL, v, d);
            if (lane >= d) v += u;
        }
        const float B    = v - s4;
        const float P128 = __shfl_sync(FULL, v, 31);   // P[128]

        // scan of extra quad totals (lanes 0..5); E = exclusive prefix
        float w = t4;
        #pragma unroll
        for (int d = 1; d < 8; d <<= 1) {
            float u = __shfl_up_sync(FULL, w, d);
            if (lane >= d) w += u;
        }
        const float E = w - t4;

        // lows: P[4l+2]=B+s2, P[4l+3]=B+s3, P[4l+4]=B_{l+1}, P[4l+5]=B_{l+1}+s1_{l+1}
        float Bn  = __shfl_down_sync(FULL, B,  1);
        float s1n = __shfl_down_sync(FULL, s1, 1);
        const float t1_0 = __shfl_sync(FULL, t1, 0);
        if (lane == 31) { Bn = P128; s1n = t1_0; }     // quad 32

        // highs: quads l+5 (comp3) and l+6 (comps 0..2)
        float B5   = __shfl_down_sync(FULL, B,  5);
        float s3_5 = __shfl_down_sync(FULL, s3, 5);
        float B6   = __shfl_down_sync(FULL, B,  6);
        float s1_6 = __shfl_down_sync(FULL, s1, 6);
        float s2_6 = __shfl_down_sync(FULL, s2, 6);

        const float E5x  = __shfl_sync(FULL, E,  lane - 27);
        const float t3_x = __shfl_sync(FULL, t3, lane - 27);
        const float E6x  = __shfl_sync(FULL, E,  lane - 26);
        const float t1_x = __shfl_sync(FULL, t1, lane - 26);
        const float t2_x = __shfl_sync(FULL, t2, lane - 26);
        if (lane >= 27) { B5 = P128 + E5x; s3_5 = t3_x; }
        if (lane >= 26) { B6 = P128 + E6x; s1_6 = t1_x; s2_6 = t2_x; }

        float4 o;
        o.x = (B5 + s3_5) - (B + s2);      // m=4l
        o.y =  B6         - (B + s3);      // m=4l+1
        o.z = (B6 + s1_6) -  Bn;           // m=4l+2
        o.w = (B6 + s2_6) - (Bn + s1n);    // m=4l+3

        *reinterpret_cast<float4*>(
            outg + (size_t)(tileY + r) * W + tileX + 4 * lane) = o;
    }
}

extern "C" void kernel_launch(void* const* d_in, const int* in_sizes, int n_in,
                              void* d_out, int out_size)
{
    const float* x = (const float*)d_in[0];
    float* out = (float*)d_out;

    dim3 grid(W / TX, H / TY, NB);   // (16, 64, 8) = 8192 blocks
    box_filter_kernel<<<grid, THREADS>>>(x, out);
}

// round 12
// speedup vs baseline: 1.2791x; 1.2791x over previous
#include <cuda_runtime.h>
#include <cuda_bf16.h>
#include <cstdint>

// 21x21 circular box filter on (8,1,2048,2048) fp32, separable, fused.
// Phase A: vertical running box-sums global -> smem (thread per halo column),
//          21-deep register ring (each input row loaded once). Thread->column
//          map shifted by 22 so every warp's LDG is one aligned 128B line.
// Phase B: horizontal box-sums via warp prefix scan, direct float4 stores.

#define H  2048
#define W  2048
#define NB 8
#define R  10
#define KW (2*R + 1)        // 21
#define TX 128
#define TY 32
#define NC (TX + 2*R)       // 148 halo columns
#define CSHIFT 22           // thread t -> column t-22: warp loads line-aligned
#define VS 152              // smem row stride (floats), 16B-aligned rows
#define THREADS 256

__global__ __launch_bounds__(THREADS, 6)
void box_filter_kernel(const float* __restrict__ in, float* __restrict__ out)
{
    __shared__ float vert[TY * VS];   // 32*152*4 = 19,456 B

    const int t  = threadIdx.x;
    const int bx = blockIdx.x;
    const int by = blockIdx.y;
    const int bz = blockIdx.z;

    const float* img  = in  + (size_t)bz * (size_t)(H * W);
    float*       outg = out + (size_t)bz * (size_t)(H * W);

    const int tileX = bx * TX;
    const int tileY = by * TY;

    // ---------------- Phase A: vertical running sums (global -> smem) ---------
    // Column c = t - 22 (c in [0,148)); gx = tileX + t - 32 -> warp w loads the
    // aligned 128B line [tileX - 32 + 32w, +32 floats). Ring buffer: each of the
    // 52 input rows loaded exactly once per column.
    if (t >= CSHIFT && t < CSHIFT + NC) {
        const int c  = t - CSHIFT;
        const int gx = (tileX + c - R) & (W - 1);
        const int y0 = tileY - R;
        const float* colp = img + gx;

        float buf[KW];
        float s = 0.0f;

        if (y0 >= 0 && y0 + TY + 2 * R <= H) {
            // Interior: wrap-free, immediate offsets off one base pointer.
            const float* p = colp + (size_t)y0 * W;

            #pragma unroll
            for (int j = 0; j < KW; j++) { buf[j] = p[j * W]; s += buf[j]; }
            vert[c] = s;

            #pragma unroll
            for (int i = 1; i < TY; i++) {
                const int slot = (i - 1) % KW;       // compile-time after unroll
                const float nv = p[(i + 2 * R) * W];
                s += nv - buf[slot];
                buf[slot] = nv;
                vert[i * VS + c] = s;
            }
        } else {
            // Boundary tiles (by==0 or by==63): masked row addressing.
            #pragma unroll
            for (int j = 0; j < KW; j++) {
                buf[j] = colp[((y0 + j) & (H - 1)) * W];
                s += buf[j];
            }
            vert[c] = s;

            #pragma unroll
            for (int i = 1; i < TY; i++) {
                const int slot = (i - 1) % KW;
                const float nv = colp[((y0 + 2 * R + i) & (H - 1)) * W];
                s += nv - buf[slot];
                buf[slot] = nv;
                vert[i * VS + c] = s;
            }
        }
    }
    __syncthreads();

    // ---------------- Phase B: horizontal sums via warp scan, direct store ----
    // Warp per row (8 warps x 4 rows). Row data a[c]=vert[r][c], c=0..147.
    // out[x] = P[x+21] - P[x], P = exclusive prefix of a.
    const unsigned FULL = 0xffffffffu;
    const int lane = t & 31;
    const int wp   = t >> 5;

    #pragma unroll
    for (int rr = 0; rr < TY / 8; rr++) {
        const int r = wp * (TY / 8) + rr;
        const float* row = vert + r * VS;

        float4 q = *reinterpret_cast<const float4*>(row + 4 * lane);
        float  e = (lane < 20) ? row[128 + lane] : 0.0f;

        const float s1 = q.x;
        const float s2 = s1 + q.y;
        const float s3 = s2 + q.z;
        const float s4 = s3 + q.w;

        // inclusive scan of quad totals -> v;  B = P[4*lane]
        float v = s4;
        #pragma unroll
        for (int d = 1; d < 32; d <<= 1) {
            float u = __shfl_up_sync(FULL, v, d);
            if (lane >= d) v += u;
        }
        const float B = v - s4;

        // inclusive scan of extras -> w  (w[l] = sum a[128..128+l])
        float w = e;
        #pragma unroll
        for (int d = 1; d < 32; d <<= 1) {
            float u = __shfl_up_sync(FULL, w, d);
            if (lane >= d) w += u;
        }
        const float P128 = __shfl_sync(FULL, v, 31);   // P[128]

        // P[4l+21+j] from lane l+5
        const float Bp  = __shfl_down_sync(FULL, B,  5);
        const float s1p = __shfl_down_sync(FULL, s1, 5);
        const float s2p = __shfl_down_sync(FULL, s2, 5);
        const float s3p = __shfl_down_sync(FULL, s3, 5);
        const float s4p = __shfl_down_sync(FULL, s4, 5);

        // tail (lanes 27..31): P[idx] = P128 + T[idx-128]
        const int base = 4 * (lane - 27);
        const float w0 = __shfl_sync(FULL, w, (base + 0) & 31);
        const float w1 = __shfl_sync(FULL, w, (base + 1) & 31);
        const float w2 = __shfl_sync(FULL, w, (base + 2) & 31);
        const float w3 = __shfl_sync(FULL, w, (base + 3) & 31);

        const bool tail = (lane >= 27);
        const float u0 = tail ? (P128 + w0) : (Bp + s1p);
        const float u1 = tail ? (P128 + w1) : (Bp + s2p);
        const float u2 = tail ? (P128 + w2) : (Bp + s3p);
        const float u3 = tail ? (P128 + w3) : (Bp + s4p);

        float4 o;
        o.x = u0 - B;
        o.y = u1 - (B + s1);
        o.z = u2 - (B + s2);
        o.w = u3 - (B + s3);

        *reinterpret_cast<float4*>(
            outg + (size_t)(tileY + r) * W + tileX + 4 * lane) = o;
    }
}

extern "C" void kernel_launch(void* const* d_in, const int* in_sizes, int n_in,
                              void* d_out, int out_size)
{
    const float* x = (const float*)d_in[0];
    float* out = (float*)d_out;

    dim3 grid(W / TX, H / TY, NB);   // (16, 64, 8) = 8192 blocks
    box_filter_kernel<<<grid, THREADS>>>(x, out);
}